// round 9
// baseline (speedup 1.0000x reference)
#include <cuda_runtime.h>
#include <cuda.h>
#include <cstdint>

#define BB     16
#define CC     3
#define HH     512
#define WW     512
#define NH     63
#define NW     63
#define NN     (NH * NW)          // 3969
#define FDIM   768
#define KNB    8

#define TPB    256

// tile = 2x4 patches
#define TI     2
#define TJ     4
#define ITILES 32                 // i0 = it*2, 0..62
#define JTILES 16                 // j0 = jt*4, 0..60
#define TILES  (BB * ITILES * JTILES)   // 8192
#define TILES_PER_CTA 8
#define PATCH_CTAS (TILES / TILES_PER_CTA)  // 1024

#define SROWS  (TI * 8 + 8)       // 24
#define SCOLS  (TJ * 8 + 8)       // 40
#define STRIPE_FLOATS (CC * SROWS * SCOLS)   // 2880
#define STRIPE_BYTES  (STRIPE_FLOATS * 4)    // 11520
#define OUT_TILE_BYTES (TI * TJ * FDIM * 4)  // 24576

// dynamic smem layout
#define OFF_STRIPE0  0
#define OFF_STRIPE1  STRIPE_BYTES                    // 11520
#define OFF_OUT0     (2 * STRIPE_BYTES)              // 23040
#define OFF_OUT1     (OFF_OUT0 + OUT_TILE_BYTES)     // 47616
#define OFF_BARS     (OFF_OUT1 + OUT_TILE_BYTES)     // 72192
#define SMEM_DYN     (OFF_BARS + 32)                 // 72224

#define POS_FLOATS   (BB * NN * 2)                  // 127,008
#define EDGE_FLOATS  (BB * 2 * NN * KNB)            // 1,016,064
#define EXTRA_FLOATS (POS_FLOATS + EDGE_FLOATS)     // 1,143,072

#define CX(a, b) { int _lo = min(a, b); b = max(a, b); a = _lo; }

__device__ __forceinline__ uint32_t smem_u32(const void* p) {
    uint32_t a;
    asm("{ .reg .u64 t; cvta.to.shared.u64 t, %1; cvt.u32.u64 %0, t; }"
        : "=r"(a) : "l"(p));
    return a;
}

// ---------------------------------------------------------------------------
// 1024 persistent CTAs. Each handles 8 tiles (2x4 patches):
//   TMA stripe load (double-buffered, 2 ahead) -> LDS.64/STS.64 reshuffle into
//   patch-ordered SMEM outbuf -> cp.async.bulk 12KB stores (async engine; no
//   STG, no store wavefronts). Then a grid-stride tail writes positions +
//   edge_index (register kNN via sorted insertion network; key = d2*4096+idx
//   reproduces top_k(-d2)'s (d2 asc, idx asc) ordering).
// ---------------------------------------------------------------------------
__global__ void __launch_bounds__(TPB)
fused_kernel(const __grid_constant__ CUtensorMap tmap,
             float* __restrict__ out)
{
    extern __shared__ __align__(128) unsigned char smem[];
    float2*   s_stripe[2];
    float2*   s_out[2];
    s_stripe[0] = (float2*)(smem + OFF_STRIPE0);
    s_stripe[1] = (float2*)(smem + OFF_STRIPE1);
    s_out[0]    = (float2*)(smem + OFF_OUT0);
    s_out[1]    = (float2*)(smem + OFF_OUT1);
    uint32_t mb = smem_u32(smem + OFF_BARS);

    int bid = blockIdx.x;

    if (threadIdx.x == 0) {
        asm volatile("mbarrier.init.shared.b64 [%0], 1;" :: "r"(mb)     : "memory");
        asm volatile("mbarrier.init.shared.b64 [%0], 1;" :: "r"(mb + 8) : "memory");
        asm volatile("fence.proxy.async.shared::cta;" ::: "memory");
    }
    __syncthreads();

    int tile0 = bid * TILES_PER_CTA;

    auto issue_load = [&](int q) {      // thread 0 only
        int tile = tile0 + q;
        int b  = tile >> 9;             // /512
        int rr = tile & 511;
        int it = rr >> 4;               // 0..31
        int jt = rr & 15;               // 0..15
        uint32_t bar = mb + (q & 1) * 8;
        uint32_t dst = smem_u32(smem) + ((q & 1) ? OFF_STRIPE1 : OFF_STRIPE0);
        asm volatile("mbarrier.arrive.expect_tx.shared.b64 _, [%0], %1;"
                     :: "r"(bar), "r"((uint32_t)STRIPE_BYTES) : "memory");
        asm volatile(
            "cp.async.bulk.tensor.3d.shared::cta.global.tile.mbarrier::complete_tx::bytes "
            "[%0], [%1, {%2, %3, %4}], [%5];"
            :: "r"(dst), "l"(&tmap),
               "r"(jt * 32), "r"(it * 16), "r"(b * CC), "r"(bar)
            : "memory");
    };

    if (threadIdx.x == 0) { issue_load(0); issue_load(1); }

    int w    = threadIdx.x >> 5;        // warp -> patch p (8 patches/tile)
    int lane = threadIdx.x & 31;
    int pi   = w >> 2;                  // 0..1
    int pj   = w & 3;                   // 0..3

    for (int q = 0; q < TILES_PER_CTA; q++) {
        int tile = tile0 + q;
        int b  = tile >> 9;
        int rr = tile & 511;
        int it = rr >> 4;
        int jt = rr & 15;

        // wait stripe (all threads)
        uint32_t bar = mb + (q & 1) * 8;
        uint32_t ph  = (q >> 1) & 1;
        uint32_t done = 0;
        while (!done) {
            asm volatile(
                "{ .reg .pred p;"
                "  mbarrier.try_wait.parity.acquire.cta.shared::cta.b64 p, [%1], %2, 0x989680;"
                "  selp.b32 %0, 1, 0, p; }"
                : "=r"(done) : "r"(bar), "r"(ph) : "memory");
        }
        // outbuf[q&1] must be fully read by TMA (tile q-2's group done)
        if (threadIdx.x == 0 && q >= 2)
            asm volatile("cp.async.bulk.wait_group.read 1;" ::: "memory");
        __syncthreads();

        // emit: patch p = (pi,pj); 384 float2 per patch, 12 warp-iters.
        // lane map: vh = lane&7 (float2 col within 16-float row), u spans
        // 4 values per instr -> 2-way LDS conflicts max.
        const float2* sin  = s_stripe[q & 1];
        float2*       sout = s_out[q & 1] + (w * 384);
        #pragma unroll
        for (int itr = 0; itr < 12; itr++) {
            int r2 = itr * 32 + lane;          // 0..383
            int vh = r2 & 7;
            int u  = (r2 >> 3) & 15;
            int c  = r2 >> 7;
            int fidx = (c * SROWS + pi * 8 + u) * SCOLS + pj * 8;  // even
            float2 v = sin[(fidx >> 1) + vh];
            sout[r2] = v;
        }

        __syncthreads();
        if (threadIdx.x == 0) {
            asm volatile("fence.proxy.async.shared::cta;" ::: "memory");
            int i0 = it * TI;
            int j0 = jt * TJ;
            int npj = min(TJ, NW - j0);                    // 4 or 3
            uint32_t sbase = smem_u32(smem) + ((q & 1) ? OFF_OUT1 : OFF_OUT0);
            #pragma unroll
            for (int r = 0; r < TI; r++) {
                if (i0 + r >= NH) break;
                const char* gdst = (const char*)out +
                    (long long)(b * NN + (i0 + r) * NW + j0) * (FDIM * 4);
                asm volatile("cp.async.bulk.global.shared::cta.bulk_group [%0], [%1], %2;"
                             :: "l"(gdst), "r"(sbase + r * (TJ * FDIM * 4)),
                                "r"((uint32_t)(npj * FDIM * 4)) : "memory");
            }
            asm volatile("cp.async.bulk.commit_group;" ::: "memory");
            if (q + 2 < TILES_PER_CTA) issue_load(q + 2);
        }
    }
    if (threadIdx.x == 0)
        asm volatile("cp.async.bulk.wait_group 0;" ::: "memory");

    // ---- pos/edge tail (grid-stride over all patch CTAs) ----
    const long long P0 = (long long)BB * NN * FDIM;
    for (int e = bid * TPB + threadIdx.x; e < EXTRA_FLOATS;
         e += PATCH_CTAS * TPB) {
        if (e < POS_FLOATS) {
            int n = (e >> 1) % NN;
            out[P0 + e] = (float)((e & 1) ? (n % NW) : (n / NW));
            continue;
        }
        int e2 = e - POS_FLOATS;
        int r  = e2 % (2 * NN * KNB);
        float v;
        if (r < NN * KNB) {
            v = (float)(r >> 3);                 // src row: node id
        } else {
            int qq = r - NN * KNB;
            int n = qq >> 3;
            int m = qq & 7;
            int i = n / NW;
            int j = n % NW;

            int t0 = 0x7fffffff, t1 = 0x7fffffff, t2 = 0x7fffffff, t3 = 0x7fffffff;
            int t4 = 0x7fffffff, t5 = 0x7fffffff, t6 = 0x7fffffff, t7 = 0x7fffffff;
            #pragma unroll
            for (int di = -2; di <= 2; di++) {
                #pragma unroll
                for (int dj = -2; dj <= 2; dj++) {
                    if (di == 0 && dj == 0) continue;
                    int ii = i + di;
                    int jj = j + dj;
                    bool ok = (ii >= 0) & (ii < NH) & (jj >= 0) & (jj < NW);
                    int key = ok ? ((di*di + dj*dj) * 4096 + (ii * NW + jj))
                                 : 0x7fffffff;
                    int t8 = key;
                    CX(t7, t8); CX(t6, t7); CX(t5, t6); CX(t4, t5);
                    CX(t3, t4); CX(t2, t3); CX(t1, t2); CX(t0, t1);
                }
            }
            int a0 = (m & 1) ? t1 : t0;
            int a1 = (m & 1) ? t3 : t2;
            int a2 = (m & 1) ? t5 : t4;
            int a3 = (m & 1) ? t7 : t6;
            int b0 = (m & 2) ? a1 : a0;
            int b1 = (m & 2) ? a3 : a2;
            int sel = (m & 4) ? b1 : b0;
            v = (float)(sel & 4095);
        }
        out[P0 + POS_FLOATS + e2] = v;
    }
}

// ---------------------------------------------------------------------------
extern "C" void kernel_launch(void* const* d_in, const int* in_sizes, int n_in,
                              void* d_out, int out_size)
{
    const float* x = (const float*)d_in[0];
    float* out = (float*)d_out;

    typedef CUresult (*EncodeFn)(
        CUtensorMap*, CUtensorMapDataType, cuuint32_t, void*,
        const cuuint64_t*, const cuuint64_t*, const cuuint32_t*,
        const cuuint32_t*, CUtensorMapInterleave, CUtensorMapSwizzle,
        CUtensorMapL2promotion, CUtensorMapFloatOOBfill);
    EncodeFn encode = nullptr;
    cudaGetDriverEntryPoint("cuTensorMapEncodeTiled", (void**)&encode,
                            cudaEnableDefault, nullptr);

    CUtensorMap tmap;
    cuuint64_t dims[3]    = {WW, HH, (cuuint64_t)(BB * CC)};
    cuuint64_t strides[2] = {WW * sizeof(float),
                             (cuuint64_t)HH * WW * sizeof(float)};
    cuuint32_t box[3]     = {SCOLS, SROWS, CC};   // 40 x 24 x 3 floats
    cuuint32_t estr[3]    = {1, 1, 1};
    encode(&tmap, CU_TENSOR_MAP_DATA_TYPE_FLOAT32, 3, (void*)x,
           dims, strides, box, estr,
           CU_TENSOR_MAP_INTERLEAVE_NONE, CU_TENSOR_MAP_SWIZZLE_NONE,
           CU_TENSOR_MAP_L2_PROMOTION_L2_128B,
           CU_TENSOR_MAP_FLOAT_OOB_FILL_NONE);

    cudaFuncSetAttribute(fused_kernel,
                         cudaFuncAttributeMaxDynamicSharedMemorySize, SMEM_DYN);
    fused_kernel<<<PATCH_CTAS, TPB, SMEM_DYN>>>(tmap, out);
}

// round 10
// speedup vs baseline: 1.1714x; 1.1714x over previous
#include <cuda_runtime.h>
#include <cuda.h>
#include <cstdint>

#define BB     16
#define CC     3
#define HH     512
#define WW     512
#define NH     63
#define NW     63
#define NN     (NH * NW)          // 3969
#define FDIM   768
#define KNB    8
#define F4PER  192

#define TPB    256

// tile = 4x4 patches; stripe = 3ch x 40 x 40 floats = 19200 B
#define TI     4
#define TJ     4
#define ITILES 16
#define JTILES 16
#define TILES  (BB * ITILES * JTILES)   // 4096
#define TILES_PER_CTA 4
#define PATCH_CTAS (TILES / TILES_PER_CTA)  // 1024

#define SROWS  40
#define SCOLS  40
#define STRIPE_FLOATS (CC * SROWS * SCOLS)  // 4800
#define STRIPE_BYTES  (STRIPE_FLOATS * 4)   // 19200

#define NBUF   3
#define OFF_BARS (NBUF * STRIPE_BYTES)      // 57600
#define SMEM_DYN (OFF_BARS + NBUF * 8)      // 57624

#define POS_FLOATS   (BB * NN * 2)                  // 127,008
#define EDGE_FLOATS  (BB * 2 * NN * KNB)            // 1,016,064
#define EXTRA_FLOATS (POS_FLOATS + EDGE_FLOATS)     // 1,143,072
#define EXTRA_BLOCKS ((EXTRA_FLOATS + TPB - 1) / TPB)   // 4,466

#define CX(a, b) { int _lo = min(a, b); b = max(a, b); a = _lo; }

__device__ __forceinline__ uint32_t smem_u32(const void* p) {
    uint32_t a;
    asm("{ .reg .u64 t; cvta.to.shared.u64 t, %1; cvt.u32.u64 %0, t; }"
        : "=r"(a) : "l"(p));
    return a;
}

// ---------------------------------------------------------------------------
// One fused kernel (R7 architecture + triple-buffered stripes).
//  blocks [0, PATCH_CTAS): persistent patch movers, 4 tiles each.
//    Stripe loads are TMA, 3 buffers, issued 2 tiles ahead; emit is
//    LDS.128 (2-way max) -> STG.128 streaming stores.
//  blocks [PATCH_CTAS, ...): positions + edge_index (register kNN via sorted
//    insertion network; key = d2*4096+idx reproduces top_k(-d2)'s
//    (d2 asc, idx asc) ordering).
// ---------------------------------------------------------------------------
__global__ void __launch_bounds__(TPB)
fused_kernel(const __grid_constant__ CUtensorMap tmap,
             float* __restrict__ out)
{
    extern __shared__ __align__(128) unsigned char smem[];

    int bid = blockIdx.x;

    if (bid >= PATCH_CTAS) {
        int e = (bid - PATCH_CTAS) * TPB + threadIdx.x;
        if (e >= EXTRA_FLOATS) return;

        const long long P0 = (long long)BB * NN * FDIM;

        if (e < POS_FLOATS) {
            int n = (e >> 1) % NN;
            out[P0 + e] = (float)((e & 1) ? (n % NW) : (n / NW));
            return;
        }

        int e2 = e - POS_FLOATS;
        int r  = e2 % (2 * NN * KNB);
        float v;
        if (r < NN * KNB) {
            v = (float)(r >> 3);                    // src row: node id
        } else {
            int q = r - NN * KNB;
            int n = q >> 3;
            int m = q & 7;
            int i = n / NW;
            int j = n % NW;

            int t0 = 0x7fffffff, t1 = 0x7fffffff, t2 = 0x7fffffff, t3 = 0x7fffffff;
            int t4 = 0x7fffffff, t5 = 0x7fffffff, t6 = 0x7fffffff, t7 = 0x7fffffff;
            #pragma unroll
            for (int di = -2; di <= 2; di++) {
                #pragma unroll
                for (int dj = -2; dj <= 2; dj++) {
                    if (di == 0 && dj == 0) continue;
                    int ii = i + di;
                    int jj = j + dj;
                    bool ok = (ii >= 0) & (ii < NH) & (jj >= 0) & (jj < NW);
                    int key = ok ? ((di*di + dj*dj) * 4096 + (ii * NW + jj))
                                 : 0x7fffffff;
                    int t8 = key;
                    CX(t7, t8); CX(t6, t7); CX(t5, t6); CX(t4, t5);
                    CX(t3, t4); CX(t2, t3); CX(t1, t2); CX(t0, t1);
                }
            }
            int a0 = (m & 1) ? t1 : t0;
            int a1 = (m & 1) ? t3 : t2;
            int a2 = (m & 1) ? t5 : t4;
            int a3 = (m & 1) ? t7 : t6;
            int b0 = (m & 2) ? a1 : a0;
            int b1 = (m & 2) ? a3 : a2;
            int sel = (m & 4) ? b1 : b0;
            v = (float)(sel & 4095);
        }
        out[P0 + POS_FLOATS + e2] = v;
        return;
    }

    // ---- persistent patch mover ----
    uint32_t sbase = smem_u32(smem);
    uint32_t mb    = sbase + OFF_BARS;

    if (threadIdx.x == 0) {
        #pragma unroll
        for (int s = 0; s < NBUF; s++)
            asm volatile("mbarrier.init.shared.b64 [%0], 1;"
                         :: "r"(mb + s * 8) : "memory");
        asm volatile("fence.proxy.async.shared::cta;" ::: "memory");
    }
    __syncthreads();

    int tile0 = bid * TILES_PER_CTA;

    auto issue_load = [&](int q) {   // thread 0 only
        int tile = tile0 + q;
        int b  = tile >> 8;
        int rr = tile & 255;
        int it = rr >> 4;
        int jt = rr & 15;
        int slot = q % NBUF;
        uint32_t bar = mb + slot * 8;
        uint32_t dst = sbase + slot * STRIPE_BYTES;
        asm volatile("mbarrier.arrive.expect_tx.shared.b64 _, [%0], %1;"
                     :: "r"(bar), "r"((uint32_t)STRIPE_BYTES) : "memory");
        asm volatile(
            "cp.async.bulk.tensor.3d.shared::cta.global.tile.mbarrier::complete_tx::bytes "
            "[%0], [%1, {%2, %3, %4}], [%5];"
            :: "r"(dst), "l"(&tmap),
               "r"(jt * 32), "r"(it * 32), "r"(b * CC), "r"(bar)
            : "memory");
    };

    if (threadIdx.x == 0) { issue_load(0); issue_load(1); }

    int w    = threadIdx.x >> 5;
    int lane = threadIdx.x & 31;

    for (int q = 0; q < TILES_PER_CTA; q++) {
        int tile = tile0 + q;
        int b  = tile >> 8;
        int rr = tile & 255;
        int it = rr >> 4;
        int jt = rr & 15;

        int slot = q % NBUF;
        uint32_t bar = mb + slot * 8;
        uint32_t ph  = (q / NBUF) & 1;
        const float* sin = (const float*)(smem + slot * STRIPE_BYTES);

        uint32_t done = 0;
        while (!done) {
            asm volatile(
                "{ .reg .pred p;"
                "  mbarrier.try_wait.parity.acquire.cta.shared::cta.b64 p, [%1], %2, 0x989680;"
                "  selp.b32 %0, 1, 0, p; }"
                : "=r"(done) : "r"(bar), "r"(ph) : "memory");
        }

        // emit 16 patches: warp w -> patches 2w, 2w+1
        #pragma unroll
        for (int pp = 0; pp < 2; pp++) {
            int p  = w * 2 + pp;
            int pi = p >> 2;
            int pj = p & 3;
            int i  = it * TI + pi;
            int j  = jt * TJ + pj;
            if (i < NH && j < NW) {
                float4* dst = reinterpret_cast<float4*>(out) +
                              (long long)(b * NN + i * NW + j) * F4PER;
                #pragma unroll
                for (int itr = 0; itr < 6; itr++) {
                    int r4 = itr * 32 + lane;          // 0..191
                    int c  = r4 >> 6;
                    int u  = (r4 >> 2) & 15;
                    int vg = r4 & 3;
                    const float4 v = *reinterpret_cast<const float4*>(
                        &sin[(c * SROWS + pi * 8 + u) * SCOLS + pj * 8 + vg * 4]);
                    __stcs(dst + r4, v);
                }
            }
        }

        __syncthreads();   // all reads of buf slot done before reuse
        if (threadIdx.x == 0 && q + 2 < TILES_PER_CTA) issue_load(q + 2);
    }
}

// ---------------------------------------------------------------------------
extern "C" void kernel_launch(void* const* d_in, const int* in_sizes, int n_in,
                              void* d_out, int out_size)
{
    const float* x = (const float*)d_in[0];
    float* out = (float*)d_out;

    typedef CUresult (*EncodeFn)(
        CUtensorMap*, CUtensorMapDataType, cuuint32_t, void*,
        const cuuint64_t*, const cuuint64_t*, const cuuint32_t*,
        const cuuint32_t*, CUtensorMapInterleave, CUtensorMapSwizzle,
        CUtensorMapL2promotion, CUtensorMapFloatOOBfill);
    EncodeFn encode = nullptr;
    cudaGetDriverEntryPoint("cuTensorMapEncodeTiled", (void**)&encode,
                            cudaEnableDefault, nullptr);

    CUtensorMap tmap;
    cuuint64_t dims[3]    = {WW, HH, (cuuint64_t)(BB * CC)};
    cuuint64_t strides[2] = {WW * sizeof(float),
                             (cuuint64_t)HH * WW * sizeof(float)};
    cuuint32_t box[3]     = {SCOLS, SROWS, CC};   // 40 x 40 x 3 floats
    cuuint32_t estr[3]    = {1, 1, 1};
    encode(&tmap, CU_TENSOR_MAP_DATA_TYPE_FLOAT32, 3, (void*)x,
           dims, strides, box, estr,
           CU_TENSOR_MAP_INTERLEAVE_NONE, CU_TENSOR_MAP_SWIZZLE_NONE,
           CU_TENSOR_MAP_L2_PROMOTION_L2_128B,
           CU_TENSOR_MAP_FLOAT_OOB_FILL_NONE);

    cudaFuncSetAttribute(fused_kernel,
                         cudaFuncAttributeMaxDynamicSharedMemorySize, SMEM_DYN);
    fused_kernel<<<PATCH_CTAS + EXTRA_BLOCKS, TPB, SMEM_DYN>>>(tmap, out);
}

// round 11
// speedup vs baseline: 1.2249x; 1.0457x over previous
#include <cuda_runtime.h>
#include <cuda.h>
#include <cstdint>

#define BB     16
#define CC     3
#define HH     512
#define WW     512
#define NH     63
#define NW     63
#define NN     (NH * NW)          // 3969
#define FDIM   768
#define KNB    8
#define F4PER  192

#define TPB    256

// tile = 2x4 patches; stripe = 3ch x 24 x 40 floats = 11520 B
#define TI     2
#define TJ     4
#define ITILES 32
#define JTILES 16
#define TILES  (BB * ITILES * JTILES)   // 8192
#define TILES_PER_CTA 8
#define PATCH_CTAS (TILES / TILES_PER_CTA)  // 1024

#define SROWS  24
#define SCOLS  40
#define STRIPE_FLOATS (CC * SROWS * SCOLS)  // 2880
#define STRIPE_BYTES  (STRIPE_FLOATS * 4)   // 11520

#define NBUF   2
#define OFF_BARS (NBUF * STRIPE_BYTES)      // 23040
#define SMEM_DYN (OFF_BARS + NBUF * 8)      // 23056

#define POS_FLOATS   (BB * NN * 2)                  // 127,008
#define EDGE_FLOATS  (BB * 2 * NN * KNB)            // 1,016,064
#define EXTRA_FLOATS (POS_FLOATS + EDGE_FLOATS)     // 1,143,072
#define EXTRA_BLOCKS ((EXTRA_FLOATS + TPB - 1) / TPB)   // 4,466

#define CX(a, b) { int _lo = min(a, b); b = max(a, b); a = _lo; }

__device__ __forceinline__ uint32_t smem_u32(const void* p) {
    uint32_t a;
    asm("{ .reg .u64 t; cvta.to.shared.u64 t, %1; cvt.u32.u64 %0, t; }"
        : "=r"(a) : "l"(p));
    return a;
}

// ---------------------------------------------------------------------------
// R7 architecture with small tiles for max concurrency (8 CTAs/SM):
//  blocks [0, PATCH_CTAS): persistent movers, 8 tiles (2x4 patches) each,
//    double-buffered TMA stripe loads; emit = 1 patch/warp,
//    LDS.128 (2-way max) -> STG.128 streaming stores.
//  blocks [PATCH_CTAS, ...): positions + edge_index (register kNN via sorted
//    insertion network; key = d2*4096+idx reproduces top_k(-d2)'s
//    (d2 asc, idx asc) ordering).
// ---------------------------------------------------------------------------
__global__ void __launch_bounds__(TPB)
fused_kernel(const __grid_constant__ CUtensorMap tmap,
             float* __restrict__ out)
{
    extern __shared__ __align__(128) unsigned char smem[];

    int bid = blockIdx.x;

    if (bid >= PATCH_CTAS) {
        int e = (bid - PATCH_CTAS) * TPB + threadIdx.x;
        if (e >= EXTRA_FLOATS) return;

        const long long P0 = (long long)BB * NN * FDIM;

        if (e < POS_FLOATS) {
            int n = (e >> 1) % NN;
            out[P0 + e] = (float)((e & 1) ? (n % NW) : (n / NW));
            return;
        }

        int e2 = e - POS_FLOATS;
        int r  = e2 % (2 * NN * KNB);
        float v;
        if (r < NN * KNB) {
            v = (float)(r >> 3);                    // src row: node id
        } else {
            int q = r - NN * KNB;
            int n = q >> 3;
            int m = q & 7;
            int i = n / NW;
            int j = n % NW;

            int t0 = 0x7fffffff, t1 = 0x7fffffff, t2 = 0x7fffffff, t3 = 0x7fffffff;
            int t4 = 0x7fffffff, t5 = 0x7fffffff, t6 = 0x7fffffff, t7 = 0x7fffffff;
            #pragma unroll
            for (int di = -2; di <= 2; di++) {
                #pragma unroll
                for (int dj = -2; dj <= 2; dj++) {
                    if (di == 0 && dj == 0) continue;
                    int ii = i + di;
                    int jj = j + dj;
                    bool ok = (ii >= 0) & (ii < NH) & (jj >= 0) & (jj < NW);
                    int key = ok ? ((di*di + dj*dj) * 4096 + (ii * NW + jj))
                                 : 0x7fffffff;
                    int t8 = key;
                    CX(t7, t8); CX(t6, t7); CX(t5, t6); CX(t4, t5);
                    CX(t3, t4); CX(t2, t3); CX(t1, t2); CX(t0, t1);
                }
            }
            int a0 = (m & 1) ? t1 : t0;
            int a1 = (m & 1) ? t3 : t2;
            int a2 = (m & 1) ? t5 : t4;
            int a3 = (m & 1) ? t7 : t6;
            int b0 = (m & 2) ? a1 : a0;
            int b1 = (m & 2) ? a3 : a2;
            int sel = (m & 4) ? b1 : b0;
            v = (float)(sel & 4095);
        }
        out[P0 + POS_FLOATS + e2] = v;
        return;
    }

    // ---- persistent patch mover ----
    uint32_t sbase = smem_u32(smem);
    uint32_t mb    = sbase + OFF_BARS;

    if (threadIdx.x == 0) {
        asm volatile("mbarrier.init.shared.b64 [%0], 1;" :: "r"(mb)     : "memory");
        asm volatile("mbarrier.init.shared.b64 [%0], 1;" :: "r"(mb + 8) : "memory");
        asm volatile("fence.proxy.async.shared::cta;" ::: "memory");
    }
    __syncthreads();

    int tile0 = bid * TILES_PER_CTA;

    auto issue_load = [&](int q) {   // thread 0 only
        int tile = tile0 + q;
        int b  = tile >> 9;             // / 512
        int rr = tile & 511;
        int it = rr >> 4;               // 0..31
        int jt = rr & 15;               // 0..15
        int slot = q & 1;
        uint32_t bar = mb + slot * 8;
        uint32_t dst = sbase + slot * STRIPE_BYTES;
        asm volatile("mbarrier.arrive.expect_tx.shared.b64 _, [%0], %1;"
                     :: "r"(bar), "r"((uint32_t)STRIPE_BYTES) : "memory");
        asm volatile(
            "cp.async.bulk.tensor.3d.shared::cta.global.tile.mbarrier::complete_tx::bytes "
            "[%0], [%1, {%2, %3, %4}], [%5];"
            :: "r"(dst), "l"(&tmap),
               "r"(jt * 32), "r"(it * 16), "r"(b * CC), "r"(bar)
            : "memory");
    };

    if (threadIdx.x == 0) { issue_load(0); issue_load(1); }

    int w    = threadIdx.x >> 5;        // warp -> patch (8 patches/tile)
    int lane = threadIdx.x & 31;
    int pi   = w >> 2;                  // 0..1
    int pj   = w & 3;                   // 0..3

    for (int q = 0; q < TILES_PER_CTA; q++) {
        int tile = tile0 + q;
        int b  = tile >> 9;
        int rr = tile & 511;
        int it = rr >> 4;
        int jt = rr & 15;

        int slot = q & 1;
        uint32_t bar = mb + slot * 8;
        uint32_t ph  = (q >> 1) & 1;
        const float* sin = (const float*)(smem + slot * STRIPE_BYTES);

        uint32_t done = 0;
        while (!done) {
            asm volatile(
                "{ .reg .pred p;"
                "  mbarrier.try_wait.parity.acquire.cta.shared::cta.b64 p, [%1], %2, 0x989680;"
                "  selp.b32 %0, 1, 0, p; }"
                : "=r"(done) : "r"(bar), "r"(ph) : "memory");
        }

        // emit: warp w -> patch (pi, pj)
        int i = it * TI + pi;
        int j = jt * TJ + pj;
        if (i < NH && j < NW) {
            float4* dst = reinterpret_cast<float4*>(out) +
                          (long long)(b * NN + i * NW + j) * F4PER;
            #pragma unroll
            for (int itr = 0; itr < 6; itr++) {
                int r4 = itr * 32 + lane;          // 0..191
                int c  = r4 >> 6;
                int u  = (r4 >> 2) & 15;
                int vg = r4 & 3;
                const float4 v = *reinterpret_cast<const float4*>(
                    &sin[(c * SROWS + pi * 8 + u) * SCOLS + pj * 8 + vg * 4]);
                __stcs(dst + r4, v);
            }
        }

        __syncthreads();   // all reads of buf slot done before reuse
        if (threadIdx.x == 0 && q + 2 < TILES_PER_CTA) issue_load(q + 2);
    }
}

// ---------------------------------------------------------------------------
extern "C" void kernel_launch(void* const* d_in, const int* in_sizes, int n_in,
                              void* d_out, int out_size)
{
    const float* x = (const float*)d_in[0];
    float* out = (float*)d_out;

    typedef CUresult (*EncodeFn)(
        CUtensorMap*, CUtensorMapDataType, cuuint32_t, void*,
        const cuuint64_t*, const cuuint64_t*, const cuuint32_t*,
        const cuuint32_t*, CUtensorMapInterleave, CUtensorMapSwizzle,
        CUtensorMapL2promotion, CUtensorMapFloatOOBfill);
    EncodeFn encode = nullptr;
    cudaGetDriverEntryPoint("cuTensorMapEncodeTiled", (void**)&encode,
                            cudaEnableDefault, nullptr);

    CUtensorMap tmap;
    cuuint64_t dims[3]    = {WW, HH, (cuuint64_t)(BB * CC)};
    cuuint64_t strides[2] = {WW * sizeof(float),
                             (cuuint64_t)HH * WW * sizeof(float)};
    cuuint32_t box[3]     = {SCOLS, SROWS, CC};   // 40 x 24 x 3 floats
    cuuint32_t estr[3]    = {1, 1, 1};
    encode(&tmap, CU_TENSOR_MAP_DATA_TYPE_FLOAT32, 3, (void*)x,
           dims, strides, box, estr,
           CU_TENSOR_MAP_INTERLEAVE_NONE, CU_TENSOR_MAP_SWIZZLE_NONE,
           CU_TENSOR_MAP_L2_PROMOTION_L2_128B,
           CU_TENSOR_MAP_FLOAT_OOB_FILL_NONE);

    cudaFuncSetAttribute(fused_kernel,
                         cudaFuncAttributeMaxDynamicSharedMemorySize, SMEM_DYN);
    fused_kernel<<<PATCH_CTAS + EXTRA_BLOCKS, TPB, SMEM_DYN>>>(tmap, out);
}